// round 8
// baseline (speedup 1.0000x reference)
#include <cuda_runtime.h>
#include <cuda_bf16.h>
#include <cstdint>

// NVAR feature expansion:
//   X: (8, 4, 4096) f32  ->  out: (8, 4, 3996, 231) f32
//   features per (b,r,t): [1, tap_0..tap_9, 220 degree-3 monomials (i<=j<=k)]
//   tap_k = X[b, r, t - (9-k)*2], t = tout + 100  (always in-bounds)

#define KTAPS   10
#define NMON    220
#define NF      231                 // 1 + KTAPS + NMON
#define NT_IN   4096
#define TRANS   100
#define NT_OUT  (NT_IN - TRANS)     // 3996
#define PADL    18                  // (KTAPS-1)*SKIP
#define TILE_T  32
#define NTHREADS 256
#define TPB      5                  // tiles per block (125 = 25 * 5)
#define TILE_WORDS (TILE_T * NF)    // 7392 floats = 29568 B per buffer
#define SMEM_BYTES (2 * TILE_WORDS * 4)

// Per-group feature ranges over [0, 231): groups 0..6 get 29, group 7 gets 28.
template <int G>
__device__ __forceinline__ void do_feats(const float (&x)[KTAPS], float* __restrict__ srow) {
    constexpr int LO = G * 29;
    constexpr int HI = (G == 7) ? NF : LO + 29;

    if (LO == 0) srow[0] = 1.0f;

    #pragma unroll
    for (int t = 0; t < KTAPS; ++t)
        if (t + 1 >= LO && t + 1 < HI) srow[t + 1] = x[t];

    // monomials in lexicographic (a<=b<=c) order, product ((xa*xb)*xc) == jnp.prod order
    int m = 0;
    #pragma unroll
    for (int a = 0; a < KTAPS; ++a) {
        #pragma unroll
        for (int b = a; b < KTAPS; ++b) {
            float xab = x[a] * x[b];            // DCE'd when no store lands in [LO,HI)
            #pragma unroll
            for (int c = b; c < KTAPS; ++c) {
                int f = 1 + KTAPS + m;
                if (f >= LO && f < HI) srow[f] = xab * x[c];
                ++m;
            }
        }
    }
}

__device__ __forceinline__ uint32_t smem_u32(const void* p) {
    uint32_t a;
    asm("{ .reg .u64 t; cvta.to.shared.u64 t, %1; cvt.u32.u64 %0, t; }" : "=r"(a) : "l"(p));
    return a;
}

__global__ __launch_bounds__(NTHREADS)
void nvar_kernel(const float* __restrict__ X, float* __restrict__ out) {
    extern __shared__ float s_buf[];            // 2 x TILE_WORDS, layout == global rows

    const int tid   = threadIdx.x;
    const int tl    = tid & (TILE_T - 1);       // time-step within tile
    const int g     = tid >> 5;                 // feature group, uniform per warp
    const int br    = blockIdx.y;               // b*4 + r, 0..31
    const int base  = blockIdx.x * (TPB * TILE_T);   // chunk of TPB tiles

    const float* Xrow = X + (size_t)br * NT_IN + (TRANS - PADL) + tl;  // + t gives tap base
    float*       Orow = out + ((size_t)br * NT_OUT) * NF;

    #pragma unroll
    for (int ti = 0; ti < TPB; ++ti) {
        const int t0    = base + ti * TILE_T;
        const int valid = min(TILE_T, NT_OUT - t0);          // 32, or 28 on last tile
        float* sb = s_buf + (ti & 1) * TILE_WORDS;

        if (tl < valid) {
            float x[KTAPS];
            #pragma unroll
            for (int t = 0; t < KTAPS; ++t)
                x[t] = __ldg(Xrow + t0 + 2 * t);             // L1-hot after first tile

            float* srow = sb + tl * NF;        // stride 231 words -> 32 distinct banks
            switch (g) {
                case 0: do_feats<0>(x, srow); break;
                case 1: do_feats<1>(x, srow); break;
                case 2: do_feats<2>(x, srow); break;
                case 3: do_feats<3>(x, srow); break;
                case 4: do_feats<4>(x, srow); break;
                case 5: do_feats<5>(x, srow); break;
                case 6: do_feats<6>(x, srow); break;
                default: do_feats<7>(x, srow); break;
            }
        }
        __syncthreads();

        if (tid == 0) {
            float* gdst = Orow + (size_t)t0 * NF;
            uint32_t src = smem_u32(sb);
            uint32_t nbytes = (uint32_t)valid * (NF * 4);    // mult of 16
            asm volatile("fence.proxy.async.shared::cta;" ::: "memory");
            asm volatile("cp.async.bulk.global.shared::cta.bulk_group [%0], [%1], %2;"
                         :: "l"(gdst), "r"(src), "r"(nbytes) : "memory");
            asm volatile("cp.async.bulk.commit_group;" ::: "memory");
            // keep at most 1 copy in flight -> buffer (ti-1)&1 is free for next iter
            asm volatile("cp.async.bulk.wait_group 1;" ::: "memory");
        }
        __syncthreads();   // publish buffer availability; copy of tile ti still in flight
    }

    if (tid == 0)
        asm volatile("cp.async.bulk.wait_group 0;" ::: "memory");
}

extern "C" void kernel_launch(void* const* d_in, const int* in_sizes, int n_in,
                              void* d_out, int out_size) {
    const float* X   = (const float*)d_in[0];
    float*       out = (float*)d_out;

    cudaFuncSetAttribute(nvar_kernel, cudaFuncAttributeMaxDynamicSharedMemorySize,
                         SMEM_BYTES);

    const int br_total = in_sizes[0] / NT_IN;                 // 32
    const int tiles    = (NT_OUT + TILE_T - 1) / TILE_T;      // 125
    dim3 grid((tiles + TPB - 1) / TPB, br_total);             // 25 x 32 = 800 blocks
    nvar_kernel<<<grid, NTHREADS, SMEM_BYTES>>>(X, out);
}